// round 5
// baseline (speedup 1.0000x reference)
#include <cuda_runtime.h>
#include <cstdint>

#define HIDDEN  4096
#define RANK    16
#define ROWS    8
#define THREADS 512
#define NWARP   16
#define TOTAL_ROWS 16384
#define TWO_OVER_PI 0.63661977236758134f

typedef unsigned long long ull;

// Dequantized weights in device scratch.
// g_Af layout: [half][k][8]  (rank-half split, contiguous 32B per (half,k))
//   g_Af[half*32768 + k*8 + r8] = A[k][half*8+r8] * sA[r] * 2/pi
// g_Bf layout: [r][c]:  B[r][c] * sB[c]
__device__ float g_Af[HIDDEN * RANK];
__device__ float g_Bf[RANK * HIDDEN];

// ---- storage-format probe (worked in R4; unchanged) ----
__device__ __forceinline__ int detect_mode(const void* p) {
    const unsigned* w = (const unsigned*)p;
    int vi = 0, vf = 0;
    #pragma unroll
    for (int i = 0; i < 32; i++) {
        unsigned u = w[i];
        int s = (int)u;
        if (s >= -127 && s <= 127) vi++;
        unsigned exp = (u >> 23) & 0xffu;
        if ((u & 0x7fffffffu) == 0u || (exp >= 127u && exp <= 133u)) vf++;
    }
    if (vi >= 24) return 1;   // int32 words
    if (vf >= 24) return 0;   // float32 words
    return 2;                 // packed int8
}
__device__ __forceinline__ float load_elem(const void* p, int mode, int i) {
    if (mode == 1) return (float)((const int*)p)[i];
    if (mode == 0) return ((const float*)p)[i];
    return (float)((const signed char*)p)[i];
}

__global__ void prep_kernel(const void* __restrict__ A, const void* __restrict__ B,
                            const float* __restrict__ sA, const float* __restrict__ sB)
{
    __shared__ int mA, mB;
    if (threadIdx.x == 0) { mA = detect_mode(A); mB = detect_mode(B); }
    __syncthreads();
    const int i = blockIdx.x * blockDim.x + threadIdx.x;   // 65536 threads
    // A: [k][r]
    {
        const int k = i >> 4, r = i & 15;
        const int half = r >> 3, r8 = r & 7;
        g_Af[half * (HIDDEN * 8) + k * 8 + r8] =
            load_elem(A, mA, i) * sA[r] * TWO_OVER_PI;
    }
    // B: [r][c]
    g_Bf[i] = load_elem(B, mB, i) * sB[i & (HIDDEN - 1)];
}

// ---- packed f32x2 primitives ----
__device__ __forceinline__ ull pack2(float a, float b) {
    ull d; asm("mov.b64 %0, {%1, %2};" : "=l"(d) : "f"(a), "f"(b)); return d;
}
__device__ __forceinline__ ull dup2(float a) { return pack2(a, a); }
__device__ __forceinline__ void unpack2(ull v, float& lo, float& hi) {
    asm("mov.b64 {%0, %1}, %2;" : "=f"(lo), "=f"(hi) : "l"(v));
}
__device__ __forceinline__ ull fma2(ull a, ull b, ull c) {
    ull d; asm("fma.rn.f32x2 %0, %1, %2, %3;" : "=l"(d) : "l"(a), "l"(b), "l"(c)); return d;
}
__device__ __forceinline__ ull mul2(ull a, ull b) {
    ull d; asm("mul.rn.f32x2 %0, %1, %2;" : "=l"(d) : "l"(a), "l"(b)); return d;
}
__device__ __forceinline__ ull add2(ull a, ull b) {
    ull d; asm("add.rn.f32x2 %0, %1, %2;" : "=l"(d) : "l"(a), "l"(b)); return d;
}

union F4U2 { float4 f4; ull u[2]; };

// Packed 2-wide sin: magic-number rint (gives q AND parity bit, no CVT/MUFU),
// Cody-Waite pi reduction, odd minimax poly. |err| ~1e-7 rel for |t| < 1e4.
__device__ __forceinline__ ull sin2(ull t) {
    const ull INVPI  = dup2(0.3183098861837907f);
    const ull MAGIC  = dup2(12582912.0f);            // 1.5 * 2^23
    const ull NMAGIC = dup2(-12582912.0f);
    const ull NPIHI  = dup2(-3.14159274101257f);     // -(float)pi
    const ull PILO   = dup2(8.742277657e-8f);        // (float)pi - pi
    ull m  = fma2(t, INVPI, MAGIC);                  // rn -> q in low mantissa
    ull qf = add2(m, NMAGIC);                        // q as float
    ull r  = fma2(qf, NPIHI, t);
    r = fma2(qf, PILO, r);                           // r = t - q*pi, |r| <= pi/2
    // parity of q = mantissa bit0 of m; fold sign into r (sin is odd)
    unsigned mlo = (unsigned)m, mhi = (unsigned)(m >> 32);
    ull sign = (((ull)(mhi << 31)) << 32) | (ull)(mlo << 31);
    r ^= sign;
    ull s = mul2(r, r);
    ull p = dup2(2.86567956e-6f);
    p = fma2(p, s, dup2(-1.98559923e-4f));
    p = fma2(p, s, dup2(8.33338592e-3f));
    p = fma2(p, s, dup2(-1.66666672e-1f));
    return fma2(p, mul2(r, s), r);
}

__global__ __launch_bounds__(THREADS, 1)
void pilora_kernel(const float* __restrict__ x, float* __restrict__ y)
{
    extern __shared__ float xs[];                    // [ROWS][HIDDEN] 128 KB
    __shared__ ull red[NWARP][ROWS * 4];             // packed partials (4 KB)
    __shared__ ull hs2[ROWS * RANK];                 // dup'd h per (row,r) (1 KB)

    const int tid  = threadIdx.x;
    const int lane = tid & 31;
    const int w    = tid >> 5;
    const size_t rowbase = (size_t)blockIdx.x * ROWS;

    // ---- stage x tile (coalesced float4) ----
    {
        const float4* xg4 = (const float4*)(x + rowbase * HIDDEN);
        float4* xs4 = (float4*)xs;
        #pragma unroll
        for (int i = 0; i < (ROWS * HIDDEN / 4) / THREADS; i++)
            xs4[tid + i * THREADS] = xg4[tid + i * THREADS];
    }
    __syncthreads();

    // ---- phase 1: rank-halved packed GEMV ----
    // warps 0-7 (tid<256) own ranks 0-7; warps 8-15 own ranks 8-15.
    {
        const int half = tid >> 8;
        const int tidh = tid & 255;
        const float* Afh = g_Af + half * (HIDDEN * 8);

        ull acc[ROWS][4];
        #pragma unroll
        for (int rr = 0; rr < ROWS; rr++)
            #pragma unroll
            for (int p = 0; p < 4; p++)
                acc[rr][p] = 0ull;

        #pragma unroll
        for (int it = 0; it < HIDDEN / 256; it++) {
            const int k = it * 256 + tidh;
            F4U2 a0, a1;
            a0.f4 = *(const float4*)(Afh + (size_t)k * 8);
            a1.f4 = *(const float4*)(Afh + (size_t)k * 8 + 4);
            #pragma unroll
            for (int rr = 0; rr < ROWS; rr++) {
                const ull xx = dup2(xs[rr * HIDDEN + k]);
                acc[rr][0] = fma2(xx, a0.u[0], acc[rr][0]);
                acc[rr][1] = fma2(xx, a0.u[1], acc[rr][1]);
                acc[rr][2] = fma2(xx, a1.u[0], acc[rr][2]);
                acc[rr][3] = fma2(xx, a1.u[1], acc[rr][3]);
            }
        }

        // warp butterfly (packed), lane 0 stores
        #pragma unroll
        for (int rr = 0; rr < ROWS; rr++) {
            #pragma unroll
            for (int p = 0; p < 4; p++) {
                ull v = acc[rr][p];
                v = add2(v, __shfl_xor_sync(0xffffffffu, v, 16));
                v = add2(v, __shfl_xor_sync(0xffffffffu, v, 8));
                v = add2(v, __shfl_xor_sync(0xffffffffu, v, 4));
                v = add2(v, __shfl_xor_sync(0xffffffffu, v, 2));
                v = add2(v, __shfl_xor_sync(0xffffffffu, v, 1));
                if (lane == 0) red[w][rr * 4 + p] = v;
            }
        }
    }
    __syncthreads();

    // combine 8 warps per half; store dup'd h into hs2
    if (tid < 64) {
        const int half = tid >> 5;                   // 0: ranks 0-7, 1: ranks 8-15
        const int idx  = tid & 31;                   // row*4 + p
        const int row  = idx >> 2, p = idx & 3;
        ull s = 0ull;
        #pragma unroll
        for (int ww = 0; ww < 8; ww++) s = add2(s, red[half * 8 + ww][idx]);
        float lo, hi; unpack2(s, lo, hi);
        const int rb = half * 8 + p * 2;
        hs2[row * RANK + rb]     = dup2(lo);
        hs2[row * RANK + rb + 1] = dup2(hi);
    }
    __syncthreads();

    // ---- phase 2: packed rank-16 GEMM + sin epilogue ----
    #pragma unroll
    for (int i = 0; i < 2; i++) {
        const int c0 = i * 2048 + tid * 4;

        ull acc2[ROWS][2];
        #pragma unroll
        for (int rr = 0; rr < ROWS; rr++) { acc2[rr][0] = 0ull; acc2[rr][1] = 0ull; }

        #pragma unroll
        for (int r = 0; r < RANK; r++) {
            F4U2 b; b.f4 = *(const float4*)(g_Bf + (size_t)r * HIDDEN + c0);
            #pragma unroll
            for (int rr = 0; rr < ROWS; rr++) {
                const ull hh = hs2[rr * RANK + r];   // LDS.64 broadcast
                acc2[rr][0] = fma2(hh, b.u[0], acc2[rr][0]);
                acc2[rr][1] = fma2(hh, b.u[1], acc2[rr][1]);
            }
        }

        const ull TWO2 = dup2(2.0f);
        #pragma unroll
        for (int rr = 0; rr < ROWS; rr++) {
            F4U2 xv; xv.f4 = *(const float4*)(xs + rr * HIDDEN + c0);
            F4U2 ov;
            ov.u[0] = fma2(TWO2, sin2(acc2[rr][0]), xv.u[0]);
            ov.u[1] = fma2(TWO2, sin2(acc2[rr][1]), xv.u[1]);
            *(float4*)(y + (rowbase + rr) * HIDDEN + c0) = ov.f4;
        }
    }
}

extern "C" void kernel_launch(void* const* d_in, const int* in_sizes, int n_in,
                              void* d_out, int out_size)
{
    // Rank-order binding by size (robust; worked in R4)
    int idx[16];
    const int m = (n_in < 16) ? n_in : 16;
    for (int i = 0; i < m; i++) idx[i] = i;
    for (int i = 0; i < m; i++) {
        int best = i;
        for (int j = i + 1; j < m; j++)
            if (in_sizes[idx[j]] < in_sizes[idx[best]]) best = j;
        if (best != i) {
            int t = idx[best];
            for (int j = best; j > i; j--) idx[j] = idx[j - 1];
            idx[i] = t;
        }
    }
    const float* sA = (const float*)d_in[idx[0]];
    const float* sB = (const float*)d_in[idx[1]];
    const void*  A  = d_in[idx[2]];
    const void*  B  = d_in[idx[3]];
    const float* x  = (const float*)d_in[idx[m - 1]];
    float* y = (float*)d_out;

    prep_kernel<<<(HIDDEN * RANK) / 256, 256>>>(A, B, sA, sB);

    const size_t smem = (size_t)ROWS * HIDDEN * sizeof(float);   // 128 KB
    cudaFuncSetAttribute(pilora_kernel,
                         cudaFuncAttributeMaxDynamicSharedMemorySize, (int)smem);
    pilora_kernel<<<TOTAL_ROWS / ROWS, THREADS, smem>>>(x, y);
}

// round 6
// speedup vs baseline: 1.7123x; 1.7123x over previous
#include <cuda_runtime.h>
#include <cstdint>

#define HIDDEN  4096
#define RANK    16
#define ROWS    4
#define THREADS 256
#define NWARP   8
#define TOTAL_ROWS 16384
#define TWO_OVER_PI 0.63661977236758134f

// Dequantized weights in device scratch (no allocations).
// g_Af[k*RANK+r] = A[k][r] * sA[r] * 2/pi ;  g_Bf[r*HIDDEN+c] = B[r][c] * sB[c]
__device__ float g_Af[HIDDEN * RANK];
__device__ float g_Bf[RANK * HIDDEN];

// --- storage-format probe (pure integer tests; FTZ/fast-math immune) ---
// mode 0 = float32 words, 1 = int32 words, 2 = packed int8 bytes
__device__ __forceinline__ int detect_mode(const void* p) {
    const unsigned* w = (const unsigned*)p;
    int vi = 0, vf = 0;
    #pragma unroll
    for (int i = 0; i < 32; i++) {
        unsigned u = w[i];
        int s = (int)u;
        if (s >= -127 && s <= 127) vi++;
        unsigned exp = (u >> 23) & 0xffu;
        if ((u & 0x7fffffffu) == 0u || (exp >= 127u && exp <= 133u)) vf++;
    }
    if (vi >= 24) return 1;
    if (vf >= 24) return 0;
    return 2;
}
__device__ __forceinline__ float load_elem(const void* p, int mode, int i) {
    if (mode == 1) return (float)((const int*)p)[i];
    if (mode == 0) return ((const float*)p)[i];
    return (float)((const signed char*)p)[i];
}

__global__ void prep_kernel(const void* __restrict__ A, const void* __restrict__ B,
                            const float* __restrict__ sA, const float* __restrict__ sB)
{
    __shared__ int mA, mB;
    if (threadIdx.x == 0) { mA = detect_mode(A); mB = detect_mode(B); }
    __syncthreads();
    const int i = blockIdx.x * blockDim.x + threadIdx.x;    // 65536 threads
    g_Af[i] = load_elem(A, mA, i) * sA[i & (RANK - 1)] * TWO_OVER_PI;
    g_Bf[i] = load_elem(B, mB, i) * sB[i & (HIDDEN - 1)];
}

// sin(t): exact identity sin(t) = (-1)^q sin(t - q*pi); Cody-Waite 2-term pi;
// degree-9 odd minimax polynomial on |r| <= pi/2 (FMA pipe only).
__device__ __forceinline__ float fast_sin(float t) {
    const int qi = __float2int_rn(t * 0.3183098861837907f);
    const float q = (float)qi;
    float r = fmaf(q, -3.14159274101257f, t);
    r = fmaf(q, 8.742277657e-8f, r);
    r = (qi & 1) ? -r : r;
    const float s = r * r;
    float p = 2.86567956e-6f;
    p = fmaf(p, s, -1.98559923e-4f);
    p = fmaf(p, s,  8.33338592e-3f);
    p = fmaf(p, s, -1.66666672e-1f);
    return fmaf(p, r * s, r);
}

__global__ __launch_bounds__(THREADS, 2)          // the one change vs R4: 2 CTAs/SM
void pilora_kernel(const float* __restrict__ x, float* __restrict__ y)
{
    extern __shared__ float xs[];                 // [ROWS][HIDDEN]  64 KB
    __shared__ float red[NWARP][ROWS * RANK];
    __shared__ float hs[ROWS * RANK];

    const int tid  = threadIdx.x;
    const int lane = tid & 31;
    const int w    = tid >> 5;
    const size_t rowbase = (size_t)blockIdx.x * ROWS;

    // ---- stage x tile (coalesced float4) ----
    {
        const float4* xg4 = (const float4*)(x + rowbase * HIDDEN);
        float4* xs4 = (float4*)xs;
        #pragma unroll
        for (int i = 0; i < (ROWS * HIDDEN / 4) / THREADS; i++)
            xs4[tid + i * THREADS] = xg4[tid + i * THREADS];
    }
    __syncthreads();

    // ---- phase 1: h[row][r] = sum_k x[row][k] * Af[k][r] ----
    float acc[ROWS][RANK];
    #pragma unroll
    for (int rr = 0; rr < ROWS; rr++)
        #pragma unroll
        for (int r = 0; r < RANK; r++)
            acc[rr][r] = 0.0f;

    #pragma unroll
    for (int it = 0; it < HIDDEN / THREADS; it++) {
        const int k = it * THREADS + tid;
        const float4* arow = (const float4*)(g_Af + (size_t)k * RANK);
        const float4 a0 = arow[0], a1 = arow[1], a2 = arow[2], a3 = arow[3];
        const float av[16] = {a0.x, a0.y, a0.z, a0.w,  a1.x, a1.y, a1.z, a1.w,
                              a2.x, a2.y, a2.z, a2.w,  a3.x, a3.y, a3.z, a3.w};
        #pragma unroll
        for (int rr = 0; rr < ROWS; rr++) {
            const float xr = xs[rr * HIDDEN + k];
            #pragma unroll
            for (int r = 0; r < RANK; r++)
                acc[rr][r] = fmaf(xr, av[r], acc[rr][r]);
        }
    }

    // warp butterfly reduction; lane 0 stores per-warp partials
    #pragma unroll
    for (int rr = 0; rr < ROWS; rr++) {
        #pragma unroll
        for (int r = 0; r < RANK; r++) {
            float v = acc[rr][r];
            v += __shfl_xor_sync(0xffffffffu, v, 16);
            v += __shfl_xor_sync(0xffffffffu, v, 8);
            v += __shfl_xor_sync(0xffffffffu, v, 4);
            v += __shfl_xor_sync(0xffffffffu, v, 2);
            v += __shfl_xor_sync(0xffffffffu, v, 1);
            if (lane == 0) red[w][rr * RANK + r] = v;
        }
    }
    __syncthreads();

    if (tid < ROWS * RANK) {
        float h = 0.0f;
        #pragma unroll
        for (int ww = 0; ww < NWARP; ww++) h += red[ww][tid];
        hs[tid] = h;                       // sA and 2/pi already folded into Af
    }
    __syncthreads();

    // ---- phase 2: y = x + 2*sin( sum_r hs[row][r] * Bf[r][c] ) ----
    #pragma unroll
    for (int i = 0; i < 4; i++) {
        const int c0 = w * 512 + i * 128 + lane * 4;

        float acc2[ROWS][4];
        #pragma unroll
        for (int rr = 0; rr < ROWS; rr++)
            #pragma unroll
            for (int j = 0; j < 4; j++)
                acc2[rr][j] = 0.0f;

        #pragma unroll
        for (int r = 0; r < RANK; r++) {
            const float4 bv = *(const float4*)(g_Bf + (size_t)r * HIDDEN + c0);
            const float b[4] = {bv.x, bv.y, bv.z, bv.w};
            #pragma unroll
            for (int rr = 0; rr < ROWS; rr++) {
                const float hr = hs[rr * RANK + r];       // smem broadcast
                #pragma unroll
                for (int j = 0; j < 4; j++)
                    acc2[rr][j] = fmaf(hr, b[j], acc2[rr][j]);
            }
        }

        #pragma unroll
        for (int rr = 0; rr < ROWS; rr++) {
            const float4 xv = *(const float4*)(xs + rr * HIDDEN + c0);
            float4 ov;
            ov.x = fmaf(2.0f, fast_sin(acc2[rr][0]), xv.x);
            ov.y = fmaf(2.0f, fast_sin(acc2[rr][1]), xv.y);
            ov.z = fmaf(2.0f, fast_sin(acc2[rr][2]), xv.z);
            ov.w = fmaf(2.0f, fast_sin(acc2[rr][3]), xv.w);
            *(float4*)(y + (rowbase + rr) * HIDDEN + c0) = ov;
        }
    }
}

extern "C" void kernel_launch(void* const* d_in, const int* in_sizes, int n_in,
                              void* d_out, int out_size)
{
    // Rank-order binding by size (robust; validated in R4)
    int idx[16];
    const int m = (n_in < 16) ? n_in : 16;
    for (int i = 0; i < m; i++) idx[i] = i;
    for (int i = 0; i < m; i++) {
        int best = i;
        for (int j = i + 1; j < m; j++)
            if (in_sizes[idx[j]] < in_sizes[idx[best]]) best = j;
        if (best != i) {
            int t = idx[best];
            for (int j = best; j > i; j--) idx[j] = idx[j - 1];
            idx[i] = t;
        }
    }
    const float* sA = (const float*)d_in[idx[0]];
    const float* sB = (const float*)d_in[idx[1]];
    const void*  A  = d_in[idx[2]];
    const void*  B  = d_in[idx[3]];
    const float* x  = (const float*)d_in[idx[m - 1]];
    float* y = (float*)d_out;

    prep_kernel<<<(HIDDEN * RANK) / 256, 256>>>(A, B, sA, sB);

    const size_t smem = (size_t)ROWS * HIDDEN * sizeof(float);   // 64 KB
    cudaFuncSetAttribute(pilora_kernel,
                         cudaFuncAttributeMaxDynamicSharedMemorySize, (int)smem);
    pilora_kernel<<<TOTAL_ROWS / ROWS, THREADS, smem>>>(x, y);
}

// round 7
// speedup vs baseline: 1.7125x; 1.0001x over previous
#include <cuda_runtime.h>
#include <cstdint>

#define HIDDEN  4096
#define RANK    16
#define ROWS    4
#define THREADS 256
#define NWARP   8
#define TOTAL_ROWS 16384
#define TWO_OVER_PI 0.63661977236758134f

// Dequantized weights in device scratch (no allocations).
// g_Af[k*RANK+r] = A[k][r] * sA[r] * 2/pi ;  g_Bf[r*HIDDEN+c] = B[r][c] * sB[c]
__device__ float g_Af[HIDDEN * RANK];
__device__ float g_Bf[RANK * HIDDEN];

// --- storage-format probe (pure integer tests; FTZ/fast-math immune) ---
// mode 0 = float32 words, 1 = int32 words, 2 = packed int8 bytes
__device__ __forceinline__ int detect_mode(const void* p) {
    const unsigned* w = (const unsigned*)p;
    int vi = 0, vf = 0;
    #pragma unroll
    for (int i = 0; i < 32; i++) {
        unsigned u = w[i];
        int s = (int)u;
        if (s >= -127 && s <= 127) vi++;
        unsigned exp = (u >> 23) & 0xffu;
        if ((u & 0x7fffffffu) == 0u || (exp >= 127u && exp <= 133u)) vf++;
    }
    if (vi >= 24) return 1;
    if (vf >= 24) return 0;
    return 2;
}
__device__ __forceinline__ float load_elem(const void* p, int mode, int i) {
    if (mode == 1) return (float)((const int*)p)[i];
    if (mode == 0) return ((const float*)p)[i];
    return (float)((const signed char*)p)[i];
}

__global__ void prep_kernel(const void* __restrict__ A, const void* __restrict__ B,
                            const float* __restrict__ sA, const float* __restrict__ sB)
{
    __shared__ int mA, mB;
    if (threadIdx.x == 0) { mA = detect_mode(A); mB = detect_mode(B); }
    __syncthreads();
    const int i = blockIdx.x * blockDim.x + threadIdx.x;    // 65536 threads
    g_Af[i] = load_elem(A, mA, i) * sA[i & (RANK - 1)] * TWO_OVER_PI;
    g_Bf[i] = load_elem(B, mB, i) * sB[i & (HIDDEN - 1)];
}

// sin(t): exact identity sin(t) = (-1)^q sin(t - q*pi); Cody-Waite 2-term pi;
// degree-9 odd minimax polynomial on |r| <= pi/2 (FMA pipe only).
__device__ __forceinline__ float fast_sin(float t) {
    const int qi = __float2int_rn(t * 0.3183098861837907f);
    const float q = (float)qi;
    float r = fmaf(q, -3.14159274101257f, t);
    r = fmaf(q, 8.742277657e-8f, r);
    r = (qi & 1) ? -r : r;
    const float s = r * r;
    float p = 2.86567956e-6f;
    p = fmaf(p, s, -1.98559923e-4f);
    p = fmaf(p, s,  8.33338592e-3f);
    p = fmaf(p, s, -1.66666672e-1f);
    return fmaf(p, r * s, r);
}

__global__ __launch_bounds__(THREADS, 2)          // 2 CTAs/SM (R6 win)
void pilora_kernel(const float* __restrict__ x, float* __restrict__ y)
{
    extern __shared__ float xs[];                 // [ROWS][HIDDEN]  64 KB
    __shared__ float red[NWARP][ROWS * RANK];
    __shared__ float hs[ROWS * RANK];

    const int tid  = threadIdx.x;
    const int lane = tid & 31;
    const int w    = tid >> 5;
    const size_t rowbase = (size_t)blockIdx.x * ROWS;

    // ---- stage x tile (coalesced float4) ----
    {
        const float4* xg4 = (const float4*)(x + rowbase * HIDDEN);
        float4* xs4 = (float4*)xs;
        #pragma unroll
        for (int i = 0; i < (ROWS * HIDDEN / 4) / THREADS; i++)
            xs4[tid + i * THREADS] = xg4[tid + i * THREADS];
    }
    __syncthreads();

    // ---- phase 1: h[row][r] = sum_k x[row][k] * Af[k][r] ----
    float acc[ROWS][RANK];
    #pragma unroll
    for (int rr = 0; rr < ROWS; rr++)
        #pragma unroll
        for (int r = 0; r < RANK; r++)
            acc[rr][r] = 0.0f;

    #pragma unroll
    for (int it = 0; it < HIDDEN / THREADS; it++) {
        const int k = it * THREADS + tid;
        const float4* arow = (const float4*)(g_Af + (size_t)k * RANK);
        const float4 a0 = arow[0], a1 = arow[1], a2 = arow[2], a3 = arow[3];
        const float av[16] = {a0.x, a0.y, a0.z, a0.w,  a1.x, a1.y, a1.z, a1.w,
                              a2.x, a2.y, a2.z, a2.w,  a3.x, a3.y, a3.z, a3.w};
        #pragma unroll
        for (int rr = 0; rr < ROWS; rr++) {
            const float xr = xs[rr * HIDDEN + k];
            #pragma unroll
            for (int r = 0; r < RANK; r++)
                acc[rr][r] = fmaf(xr, av[r], acc[rr][r]);
        }
    }

    // warp butterfly reduction; lane 0 stores per-warp partials
    #pragma unroll
    for (int rr = 0; rr < ROWS; rr++) {
        #pragma unroll
        for (int r = 0; r < RANK; r++) {
            float v = acc[rr][r];
            v += __shfl_xor_sync(0xffffffffu, v, 16);
            v += __shfl_xor_sync(0xffffffffu, v, 8);
            v += __shfl_xor_sync(0xffffffffu, v, 4);
            v += __shfl_xor_sync(0xffffffffu, v, 2);
            v += __shfl_xor_sync(0xffffffffu, v, 1);
            if (lane == 0) red[w][rr * RANK + r] = v;
        }
    }
    __syncthreads();

    if (tid < ROWS * RANK) {
        float h = 0.0f;
        #pragma unroll
        for (int ww = 0; ww < NWARP; ww++) h += red[ww][tid];
        hs[tid] = h;                       // sA and 2/pi already folded into Af
    }
    __syncthreads();

    // ---- NEW: hoist all 64 h values into registers (16 LDS.128 total,
    // replaces 1024 loop-invariant scalar LDS broadcasts in the i-loop) ----
    float hreg[ROWS][RANK];
    #pragma unroll
    for (int rr = 0; rr < ROWS; rr++) {
        #pragma unroll
        for (int r = 0; r < RANK; r += 4) {
            const float4 hv = *(const float4*)(hs + rr * RANK + r);
            hreg[rr][r]     = hv.x;
            hreg[rr][r + 1] = hv.y;
            hreg[rr][r + 2] = hv.z;
            hreg[rr][r + 3] = hv.w;
        }
    }

    // ---- phase 2: y = x + 2*sin( sum_r hreg[row][r] * Bf[r][c] ) ----
    #pragma unroll
    for (int i = 0; i < 4; i++) {
        const int c0 = w * 512 + i * 128 + lane * 4;

        float acc2[ROWS][4];
        #pragma unroll
        for (int rr = 0; rr < ROWS; rr++)
            #pragma unroll
            for (int j = 0; j < 4; j++)
                acc2[rr][j] = 0.0f;

        #pragma unroll
        for (int r = 0; r < RANK; r++) {
            const float4 bv = *(const float4*)(g_Bf + (size_t)r * HIDDEN + c0);
            const float b[4] = {bv.x, bv.y, bv.z, bv.w};
            #pragma unroll
            for (int rr = 0; rr < ROWS; rr++) {
                const float hr = hreg[rr][r];             // register operand
                #pragma unroll
                for (int j = 0; j < 4; j++)
                    acc2[rr][j] = fmaf(hr, b[j], acc2[rr][j]);
            }
        }

        #pragma unroll
        for (int rr = 0; rr < ROWS; rr++) {
            const float4 xv = *(const float4*)(xs + rr * HIDDEN + c0);
            float4 ov;
            ov.x = fmaf(2.0f, fast_sin(acc2[rr][0]), xv.x);
            ov.y = fmaf(2.0f, fast_sin(acc2[rr][1]), xv.y);
            ov.z = fmaf(2.0f, fast_sin(acc2[rr][2]), xv.z);
            ov.w = fmaf(2.0f, fast_sin(acc2[rr][3]), xv.w);
            *(float4*)(y + (rowbase + rr) * HIDDEN + c0) = ov;
        }
    }
}

extern "C" void kernel_launch(void* const* d_in, const int* in_sizes, int n_in,
                              void* d_out, int out_size)
{
    // Rank-order binding by size (robust; validated in R4/R6)
    int idx[16];
    const int m = (n_in < 16) ? n_in : 16;
    for (int i = 0; i < m; i++) idx[i] = i;
    for (int i = 0; i < m; i++) {
        int best = i;
        for (int j = i + 1; j < m; j++)
            if (in_sizes[idx[j]] < in_sizes[idx[best]]) best = j;
        if (best != i) {
            int t = idx[best];
            for (int j = best; j > i; j--) idx[j] = idx[j - 1];
            idx[i] = t;
        }
    }
    const float* sA = (const float*)d_in[idx[0]];
    const float* sB = (const float*)d_in[idx[1]];
    const void*  A  = d_in[idx[2]];
    const void*  B  = d_in[idx[3]];
    const float* x  = (const float*)d_in[idx[m - 1]];
    float* y = (float*)d_out;

    prep_kernel<<<(HIDDEN * RANK) / 256, 256>>>(A, B, sA, sB);

    const size_t smem = (size_t)ROWS * HIDDEN * sizeof(float);   // 64 KB
    cudaFuncSetAttribute(pilora_kernel,
                         cudaFuncAttributeMaxDynamicSharedMemorySize, (int)smem);
    pilora_kernel<<<TOTAL_ROWS / ROWS, THREADS, smem>>>(x, y);
}

// round 8
// speedup vs baseline: 1.7145x; 1.0012x over previous
#include <cuda_runtime.h>
#include <cstdint>

#define HIDDEN  4096
#define RANK    16
#define ROWS    4
#define THREADS 256
#define NWARP   8
#define TOTAL_ROWS 16384
#define TWO_OVER_PI 0.63661977236758134f

// Dequantized weights in device scratch (no allocations).
// g_Af[k*RANK+r] = A[k][r] * sA[r] * 2/pi ;  g_Bf[r*HIDDEN+c] = B[r][c] * sB[c]
__device__ float g_Af[HIDDEN * RANK];
__device__ float g_Bf[RANK * HIDDEN];

// --- storage-format probe (pure integer tests; FTZ/fast-math immune) ---
// mode 0 = float32 words, 1 = int32 words, 2 = packed int8 bytes
__device__ __forceinline__ int detect_mode(const void* p) {
    const unsigned* w = (const unsigned*)p;
    int vi = 0, vf = 0;
    #pragma unroll
    for (int i = 0; i < 32; i++) {
        unsigned u = w[i];
        int s = (int)u;
        if (s >= -127 && s <= 127) vi++;
        unsigned exp = (u >> 23) & 0xffu;
        if ((u & 0x7fffffffu) == 0u || (exp >= 127u && exp <= 133u)) vf++;
    }
    if (vi >= 24) return 1;
    if (vf >= 24) return 0;
    return 2;
}
__device__ __forceinline__ float load_elem(const void* p, int mode, int i) {
    if (mode == 1) return (float)((const int*)p)[i];
    if (mode == 0) return ((const float*)p)[i];
    return (float)((const signed char*)p)[i];
}

__global__ void prep_kernel(const void* __restrict__ A, const void* __restrict__ B,
                            const float* __restrict__ sA, const float* __restrict__ sB)
{
    __shared__ int mA, mB;
    if (threadIdx.x == 0) { mA = detect_mode(A); mB = detect_mode(B); }
    __syncthreads();
    const int i = blockIdx.x * blockDim.x + threadIdx.x;    // 65536 threads
    g_Af[i] = load_elem(A, mA, i) * sA[i & (RANK - 1)] * TWO_OVER_PI;
    g_Bf[i] = load_elem(B, mB, i) * sB[i & (HIDDEN - 1)];
}

// sin(t): exact identity sin(t) = (-1)^q sin(t - q*pi); Cody-Waite 2-term pi;
// degree-9 odd minimax polynomial on |r| <= pi/2 (FMA pipe only).
__device__ __forceinline__ float fast_sin(float t) {
    const int qi = __float2int_rn(t * 0.3183098861837907f);
    const float q = (float)qi;
    float r = fmaf(q, -3.14159274101257f, t);
    r = fmaf(q, 8.742277657e-8f, r);
    r = (qi & 1) ? -r : r;
    const float s = r * r;
    float p = 2.86567956e-6f;
    p = fmaf(p, s, -1.98559923e-4f);
    p = fmaf(p, s,  8.33338592e-3f);
    p = fmaf(p, s, -1.66666672e-1f);
    return fmaf(p, r * s, r);
}

__global__ __launch_bounds__(THREADS, 2)          // 2 CTAs/SM (R6 win)
void pilora_kernel(const float* __restrict__ x, float* __restrict__ y)
{
    extern __shared__ float xs[];                 // [ROWS][HIDDEN]  64 KB
    __shared__ float red[NWARP][ROWS * RANK];
    __shared__ float hs[ROWS * RANK];

    const int tid  = threadIdx.x;
    const int lane = tid & 31;
    const int w    = tid >> 5;
    const size_t rowbase = (size_t)blockIdx.x * ROWS;

    // ---- stage x tile (coalesced float4) ----
    {
        const float4* xg4 = (const float4*)(x + rowbase * HIDDEN);
        float4* xs4 = (float4*)xs;
        #pragma unroll
        for (int i = 0; i < (ROWS * HIDDEN / 4) / THREADS; i++)
            xs4[tid + i * THREADS] = xg4[tid + i * THREADS];
    }
    __syncthreads();

    // ---- phase 1: h[row][r] = sum_k x[row][k] * Af[k][r] ----
    float acc[ROWS][RANK];
    #pragma unroll
    for (int rr = 0; rr < ROWS; rr++)
        #pragma unroll
        for (int r = 0; r < RANK; r++)
            acc[rr][r] = 0.0f;

    #pragma unroll
    for (int it = 0; it < HIDDEN / THREADS; it++) {
        const int k = it * THREADS + tid;
        const float4* arow = (const float4*)(g_Af + (size_t)k * RANK);
        const float4 a0 = arow[0], a1 = arow[1], a2 = arow[2], a3 = arow[3];
        const float av[16] = {a0.x, a0.y, a0.z, a0.w,  a1.x, a1.y, a1.z, a1.w,
                              a2.x, a2.y, a2.z, a2.w,  a3.x, a3.y, a3.z, a3.w};
        #pragma unroll
        for (int rr = 0; rr < ROWS; rr++) {
            const float xr = xs[rr * HIDDEN + k];
            #pragma unroll
            for (int r = 0; r < RANK; r++)
                acc[rr][r] = fmaf(xr, av[r], acc[rr][r]);
        }
    }

    // warp butterfly reduction; lane 0 stores per-warp partials
    #pragma unroll
    for (int rr = 0; rr < ROWS; rr++) {
        #pragma unroll
        for (int r = 0; r < RANK; r++) {
            float v = acc[rr][r];
            v += __shfl_xor_sync(0xffffffffu, v, 16);
            v += __shfl_xor_sync(0xffffffffu, v, 8);
            v += __shfl_xor_sync(0xffffffffu, v, 4);
            v += __shfl_xor_sync(0xffffffffu, v, 2);
            v += __shfl_xor_sync(0xffffffffu, v, 1);
            if (lane == 0) red[w][rr * RANK + r] = v;
        }
    }
    __syncthreads();

    if (tid < ROWS * RANK) {
        float h = 0.0f;
        #pragma unroll
        for (int ww = 0; ww < NWARP; ww++) h += red[ww][tid];
        hs[tid] = h;                       // sA and 2/pi already folded into Af
    }
    __syncthreads();

    // ---- NEW: hoist all 64 h values into registers (16 LDS.128 total,
    // replaces 1024 loop-invariant scalar LDS broadcasts in the i-loop) ----
    float hreg[ROWS][RANK];
    #pragma unroll
    for (int rr = 0; rr < ROWS; rr++) {
        #pragma unroll
        for (int r = 0; r < RANK; r += 4) {
            const float4 hv = *(const float4*)(hs + rr * RANK + r);
            hreg[rr][r]     = hv.x;
            hreg[rr][r + 1] = hv.y;
            hreg[rr][r + 2] = hv.z;
            hreg[rr][r + 3] = hv.w;
        }
    }

    // ---- phase 2: y = x + 2*sin( sum_r hreg[row][r] * Bf[r][c] ) ----
    #pragma unroll
    for (int i = 0; i < 4; i++) {
        const int c0 = w * 512 + i * 128 + lane * 4;

        float acc2[ROWS][4];
        #pragma unroll
        for (int rr = 0; rr < ROWS; rr++)
            #pragma unroll
            for (int j = 0; j < 4; j++)
                acc2[rr][j] = 0.0f;

        #pragma unroll
        for (int r = 0; r < RANK; r++) {
            const float4 bv = *(const float4*)(g_Bf + (size_t)r * HIDDEN + c0);
            const float b[4] = {bv.x, bv.y, bv.z, bv.w};
            #pragma unroll
            for (int rr = 0; rr < ROWS; rr++) {
                const float hr = hreg[rr][r];             // register operand
                #pragma unroll
                for (int j = 0; j < 4; j++)
                    acc2[rr][j] = fmaf(hr, b[j], acc2[rr][j]);
            }
        }

        #pragma unroll
        for (int rr = 0; rr < ROWS; rr++) {
            const float4 xv = *(const float4*)(xs + rr * HIDDEN + c0);
            float4 ov;
            ov.x = fmaf(2.0f, fast_sin(acc2[rr][0]), xv.x);
            ov.y = fmaf(2.0f, fast_sin(acc2[rr][1]), xv.y);
            ov.z = fmaf(2.0f, fast_sin(acc2[rr][2]), xv.z);
            ov.w = fmaf(2.0f, fast_sin(acc2[rr][3]), xv.w);
            *(float4*)(y + (rowbase + rr) * HIDDEN + c0) = ov;
        }
    }
}

extern "C" void kernel_launch(void* const* d_in, const int* in_sizes, int n_in,
                              void* d_out, int out_size)
{
    // Rank-order binding by size (robust; validated in R4/R6)
    int idx[16];
    const int m = (n_in < 16) ? n_in : 16;
    for (int i = 0; i < m; i++) idx[i] = i;
    for (int i = 0; i < m; i++) {
        int best = i;
        for (int j = i + 1; j < m; j++)
            if (in_sizes[idx[j]] < in_sizes[idx[best]]) best = j;
        if (best != i) {
            int t = idx[best];
            for (int j = best; j > i; j--) idx[j] = idx[j - 1];
            idx[i] = t;
        }
    }
    const float* sA = (const float*)d_in[idx[0]];
    const float* sB = (const float*)d_in[idx[1]];
    const void*  A  = d_in[idx[2]];
    const void*  B  = d_in[idx[3]];
    const float* x  = (const float*)d_in[idx[m - 1]];
    float* y = (float*)d_out;

    prep_kernel<<<(HIDDEN * RANK) / 256, 256>>>(A, B, sA, sB);

    const size_t smem = (size_t)ROWS * HIDDEN * sizeof(float);   // 64 KB
    cudaFuncSetAttribute(pilora_kernel,
                         cudaFuncAttributeMaxDynamicSharedMemorySize, (int)smem);
    pilora_kernel<<<TOTAL_ROWS / ROWS, THREADS, smem>>>(x, y);
}

// round 9
// speedup vs baseline: 1.7148x; 1.0001x over previous
#include <cuda_runtime.h>
#include <cstdint>

#define HIDDEN  4096
#define RANK    16
#define ROWS    4
#define THREADS 256
#define NWARP   8
#define TOTAL_ROWS 16384
#define TWO_OVER_PI 0.63661977236758134f

// Dequantized weights in device scratch (no allocations).
// g_Af[k*RANK+r] = A[k][r] * sA[r] * 2/pi ;  g_Bf[r*HIDDEN+c] = B[r][c] * sB[c]
__device__ float g_Af[HIDDEN * RANK];
__device__ float g_Bf[RANK * HIDDEN];

// --- storage-format probe (pure integer tests; FTZ/fast-math immune) ---
// mode 0 = float32 words, 1 = int32 words, 2 = packed int8 bytes
__device__ __forceinline__ int detect_mode(const void* p) {
    const unsigned* w = (const unsigned*)p;
    int vi = 0, vf = 0;
    #pragma unroll
    for (int i = 0; i < 32; i++) {
        unsigned u = w[i];
        int s = (int)u;
        if (s >= -127 && s <= 127) vi++;
        unsigned exp = (u >> 23) & 0xffu;
        if ((u & 0x7fffffffu) == 0u || (exp >= 127u && exp <= 133u)) vf++;
    }
    if (vi >= 24) return 1;
    if (vf >= 24) return 0;
    return 2;
}
__device__ __forceinline__ float load_elem(const void* p, int mode, int i) {
    if (mode == 1) return (float)((const int*)p)[i];
    if (mode == 0) return ((const float*)p)[i];
    return (float)((const signed char*)p)[i];
}

__global__ void prep_kernel(const void* __restrict__ A, const void* __restrict__ B,
                            const float* __restrict__ sA, const float* __restrict__ sB)
{
    __shared__ int mA, mB;
    if (threadIdx.x == 0) { mA = detect_mode(A); mB = detect_mode(B); }
    __syncthreads();
    const int i = blockIdx.x * blockDim.x + threadIdx.x;    // 65536 threads
    g_Af[i] = load_elem(A, mA, i) * sA[i & (RANK - 1)] * TWO_OVER_PI;
    g_Bf[i] = load_elem(B, mB, i) * sB[i & (HIDDEN - 1)];
}

// sin(t): exact identity sin(t) = (-1)^q sin(t - q*pi); Cody-Waite 2-term pi;
// degree-9 odd minimax polynomial on |r| <= pi/2 (FMA pipe only).
__device__ __forceinline__ float fast_sin(float t) {
    const int qi = __float2int_rn(t * 0.3183098861837907f);
    const float q = (float)qi;
    float r = fmaf(q, -3.14159274101257f, t);
    r = fmaf(q, 8.742277657e-8f, r);
    r = (qi & 1) ? -r : r;
    const float s = r * r;
    float p = 2.86567956e-6f;
    p = fmaf(p, s, -1.98559923e-4f);
    p = fmaf(p, s,  8.33338592e-3f);
    p = fmaf(p, s, -1.66666672e-1f);
    return fmaf(p, r * s, r);
}

__global__ __launch_bounds__(THREADS, 2)          // 2 CTAs/SM (R6 win)
void pilora_kernel(const float* __restrict__ x, float* __restrict__ y)
{
    extern __shared__ float xs[];                 // [ROWS][HIDDEN]  64 KB
    __shared__ float red[NWARP][ROWS * RANK];
    __shared__ float hs[ROWS * RANK];

    const int tid  = threadIdx.x;
    const int lane = tid & 31;
    const int w    = tid >> 5;
    const size_t rowbase = (size_t)blockIdx.x * ROWS;

    // ---- stage x tile (coalesced float4) ----
    {
        const float4* xg4 = (const float4*)(x + rowbase * HIDDEN);
        float4* xs4 = (float4*)xs;
        #pragma unroll
        for (int i = 0; i < (ROWS * HIDDEN / 4) / THREADS; i++)
            xs4[tid + i * THREADS] = xg4[tid + i * THREADS];
    }
    __syncthreads();

    // ---- phase 1: h[row][r] = sum_k x[row][k] * Af[k][r] ----
    float acc[ROWS][RANK];
    #pragma unroll
    for (int rr = 0; rr < ROWS; rr++)
        #pragma unroll
        for (int r = 0; r < RANK; r++)
            acc[rr][r] = 0.0f;

    #pragma unroll
    for (int it = 0; it < HIDDEN / THREADS; it++) {
        const int k = it * THREADS + tid;
        const float4* arow = (const float4*)(g_Af + (size_t)k * RANK);
        const float4 a0 = arow[0], a1 = arow[1], a2 = arow[2], a3 = arow[3];
        const float av[16] = {a0.x, a0.y, a0.z, a0.w,  a1.x, a1.y, a1.z, a1.w,
                              a2.x, a2.y, a2.z, a2.w,  a3.x, a3.y, a3.z, a3.w};
        #pragma unroll
        for (int rr = 0; rr < ROWS; rr++) {
            const float xr = xs[rr * HIDDEN + k];
            #pragma unroll
            for (int r = 0; r < RANK; r++)
                acc[rr][r] = fmaf(xr, av[r], acc[rr][r]);
        }
    }

    // warp butterfly reduction; lane 0 stores per-warp partials
    #pragma unroll
    for (int rr = 0; rr < ROWS; rr++) {
        #pragma unroll
        for (int r = 0; r < RANK; r++) {
            float v = acc[rr][r];
            v += __shfl_xor_sync(0xffffffffu, v, 16);
            v += __shfl_xor_sync(0xffffffffu, v, 8);
            v += __shfl_xor_sync(0xffffffffu, v, 4);
            v += __shfl_xor_sync(0xffffffffu, v, 2);
            v += __shfl_xor_sync(0xffffffffu, v, 1);
            if (lane == 0) red[w][rr * RANK + r] = v;
        }
    }
    __syncthreads();

    if (tid < ROWS * RANK) {
        float h = 0.0f;
        #pragma unroll
        for (int ww = 0; ww < NWARP; ww++) h += red[ww][tid];
        hs[tid] = h;                       // sA and 2/pi already folded into Af
    }
    __syncthreads();

    // ---- NEW: hoist all 64 h values into registers (16 LDS.128 total,
    // replaces 1024 loop-invariant scalar LDS broadcasts in the i-loop) ----
    float hreg[ROWS][RANK];
    #pragma unroll
    for (int rr = 0; rr < ROWS; rr++) {
        #pragma unroll
        for (int r = 0; r < RANK; r += 4) {
            const float4 hv = *(const float4*)(hs + rr * RANK + r);
            hreg[rr][r]     = hv.x;
            hreg[rr][r + 1] = hv.y;
            hreg[rr][r + 2] = hv.z;
            hreg[rr][r + 3] = hv.w;
        }
    }

    // ---- phase 2: y = x + 2*sin( sum_r hreg[row][r] * Bf[r][c] ) ----
    #pragma unroll
    for (int i = 0; i < 4; i++) {
        const int c0 = w * 512 + i * 128 + lane * 4;

        float acc2[ROWS][4];
        #pragma unroll
        for (int rr = 0; rr < ROWS; rr++)
            #pragma unroll
            for (int j = 0; j < 4; j++)
                acc2[rr][j] = 0.0f;

        #pragma unroll
        for (int r = 0; r < RANK; r++) {
            const float4 bv = *(const float4*)(g_Bf + (size_t)r * HIDDEN + c0);
            const float b[4] = {bv.x, bv.y, bv.z, bv.w};
            #pragma unroll
            for (int rr = 0; rr < ROWS; rr++) {
                const float hr = hreg[rr][r];             // register operand
                #pragma unroll
                for (int j = 0; j < 4; j++)
                    acc2[rr][j] = fmaf(hr, b[j], acc2[rr][j]);
            }
        }

        #pragma unroll
        for (int rr = 0; rr < ROWS; rr++) {
            const float4 xv = *(const float4*)(xs + rr * HIDDEN + c0);
            float4 ov;
            ov.x = fmaf(2.0f, fast_sin(acc2[rr][0]), xv.x);
            ov.y = fmaf(2.0f, fast_sin(acc2[rr][1]), xv.y);
            ov.z = fmaf(2.0f, fast_sin(acc2[rr][2]), xv.z);
            ov.w = fmaf(2.0f, fast_sin(acc2[rr][3]), xv.w);
            *(float4*)(y + (rowbase + rr) * HIDDEN + c0) = ov;
        }
    }
}

extern "C" void kernel_launch(void* const* d_in, const int* in_sizes, int n_in,
                              void* d_out, int out_size)
{
    // Rank-order binding by size (robust; validated in R4/R6)
    int idx[16];
    const int m = (n_in < 16) ? n_in : 16;
    for (int i = 0; i < m; i++) idx[i] = i;
    for (int i = 0; i < m; i++) {
        int best = i;
        for (int j = i + 1; j < m; j++)
            if (in_sizes[idx[j]] < in_sizes[idx[best]]) best = j;
        if (best != i) {
            int t = idx[best];
            for (int j = best; j > i; j--) idx[j] = idx[j - 1];
            idx[i] = t;
        }
    }
    const float* sA = (const float*)d_in[idx[0]];
    const float* sB = (const float*)d_in[idx[1]];
    const void*  A  = d_in[idx[2]];
    const void*  B  = d_in[idx[3]];
    const float* x  = (const float*)d_in[idx[m - 1]];
    float* y = (float*)d_out;

    prep_kernel<<<(HIDDEN * RANK) / 256, 256>>>(A, B, sA, sB);

    const size_t smem = (size_t)ROWS * HIDDEN * sizeof(float);   // 64 KB
    cudaFuncSetAttribute(pilora_kernel,
                         cudaFuncAttributeMaxDynamicSharedMemorySize, (int)smem);
    pilora_kernel<<<TOTAL_ROWS / ROWS, THREADS, smem>>>(x, y);
}

// round 10
// speedup vs baseline: 2.0960x; 1.2223x over previous
#include <cuda_runtime.h>
#include <cstdint>

#define HIDDEN  4096
#define RANK    16
#define ROWS    4
#define THREADS 256
#define NWARP   8
#define TOTAL_ROWS 16384
#define TWO_OVER_PI 0.63661977236758134f

// Dequantized weights in device scratch (no allocations).
// g_Aft[r*HIDDEN+k] = A[k][r] * sA[r] * 2/pi   (TRANSPOSED for coalesced loads)
// g_Bf [r*HIDDEN+c] = B[r][c] * sB[c]
__device__ float g_Aft[RANK * HIDDEN];
__device__ float g_Bf[RANK * HIDDEN];

// --- storage-format probe (pure integer tests; FTZ/fast-math immune) ---
// mode 0 = float32 words, 1 = int32 words, 2 = packed int8 bytes
__device__ __forceinline__ int detect_mode(const void* p) {
    const unsigned* w = (const unsigned*)p;
    int vi = 0, vf = 0;
    #pragma unroll
    for (int i = 0; i < 32; i++) {
        unsigned u = w[i];
        int s = (int)u;
        if (s >= -127 && s <= 127) vi++;
        unsigned exp = (u >> 23) & 0xffu;
        if ((u & 0x7fffffffu) == 0u || (exp >= 127u && exp <= 133u)) vf++;
    }
    if (vi >= 24) return 1;
    if (vf >= 24) return 0;
    return 2;
}
__device__ __forceinline__ float load_elem(const void* p, int mode, int i) {
    if (mode == 1) return (float)((const int*)p)[i];
    if (mode == 0) return ((const float*)p)[i];
    return (float)((const signed char*)p)[i];
}

__global__ void prep_kernel(const void* __restrict__ A, const void* __restrict__ B,
                            const float* __restrict__ sA, const float* __restrict__ sB)
{
    __shared__ int mA, mB;
    if (threadIdx.x == 0) { mA = detect_mode(A); mB = detect_mode(B); }
    __syncthreads();
    const int i = blockIdx.x * blockDim.x + threadIdx.x;    // 65536 threads
    // A is [k][r] in memory; store transposed [r][k]
    {
        const int k = i >> 4, r = i & 15;
        g_Aft[(size_t)r * HIDDEN + k] = load_elem(A, mA, i) * sA[r] * TWO_OVER_PI;
    }
    g_Bf[i] = load_elem(B, mB, i) * sB[i & (HIDDEN - 1)];
}

// sin(t): exact identity sin(t) = (-1)^q sin(t - q*pi); Cody-Waite 2-term pi;
// degree-9 odd minimax polynomial on |r| <= pi/2 (FMA pipe only).
__device__ __forceinline__ float fast_sin(float t) {
    const int qi = __float2int_rn(t * 0.3183098861837907f);
    const float q = (float)qi;
    float r = fmaf(q, -3.14159274101257f, t);
    r = fmaf(q, 8.742277657e-8f, r);
    r = (qi & 1) ? -r : r;
    const float s = r * r;
    float p = 2.86567956e-6f;
    p = fmaf(p, s, -1.98559923e-4f);
    p = fmaf(p, s,  8.33338592e-3f);
    p = fmaf(p, s, -1.66666672e-1f);
    return fmaf(p, r * s, r);
}

__global__ __launch_bounds__(THREADS, 2)          // 2 CTAs/SM
void pilora_kernel(const float* __restrict__ x, float* __restrict__ y)
{
    extern __shared__ float xs[];                 // [ROWS][HIDDEN]  64 KB
    __shared__ float red[NWARP][ROWS * RANK];
    __shared__ float hs[ROWS * RANK];

    const int tid  = threadIdx.x;
    const int lane = tid & 31;
    const int w    = tid >> 5;
    const size_t rowbase = (size_t)blockIdx.x * ROWS;

    // ---- stage x tile (coalesced float4) ----
    {
        const float4* xg4 = (const float4*)(x + rowbase * HIDDEN);
        float4* xs4 = (float4*)xs;
        #pragma unroll
        for (int i = 0; i < (ROWS * HIDDEN / 4) / THREADS; i++)
            xs4[tid + i * THREADS] = xg4[tid + i * THREADS];
    }
    __syncthreads();

    // ---- phase 1 (restructured): coalesced A loads via transposed layout ----
    // Each thread owns 4 consecutive k per iter; A load per rank is a fully
    // coalesced LDG.128 (4 wavefronts/warp vs 16 before).
    float acc[ROWS][RANK];
    #pragma unroll
    for (int rr = 0; rr < ROWS; rr++)
        #pragma unroll
        for (int r = 0; r < RANK; r++)
            acc[rr][r] = 0.0f;

    #pragma unroll
    for (int i = 0; i < 4; i++) {
        const int k0 = w * 512 + i * 128 + lane * 4;

        float4 xv[ROWS];
        #pragma unroll
        for (int rr = 0; rr < ROWS; rr++)
            xv[rr] = *(const float4*)(xs + rr * HIDDEN + k0);

        #pragma unroll
        for (int r = 0; r < RANK; r++) {
            const float4 av = *(const float4*)(g_Aft + (size_t)r * HIDDEN + k0);
            #pragma unroll
            for (int rr = 0; rr < ROWS; rr++) {
                float t = acc[rr][r];
                t = fmaf(xv[rr].x, av.x, t);
                t = fmaf(xv[rr].y, av.y, t);
                t = fmaf(xv[rr].z, av.z, t);
                t = fmaf(xv[rr].w, av.w, t);
                acc[rr][r] = t;
            }
        }
    }

    // warp butterfly reduction; lane 0 stores per-warp partials
    #pragma unroll
    for (int rr = 0; rr < ROWS; rr++) {
        #pragma unroll
        for (int r = 0; r < RANK; r++) {
            float v = acc[rr][r];
            v += __shfl_xor_sync(0xffffffffu, v, 16);
            v += __shfl_xor_sync(0xffffffffu, v, 8);
            v += __shfl_xor_sync(0xffffffffu, v, 4);
            v += __shfl_xor_sync(0xffffffffu, v, 2);
            v += __shfl_xor_sync(0xffffffffu, v, 1);
            if (lane == 0) red[w][rr * RANK + r] = v;
        }
    }
    __syncthreads();

    if (tid < ROWS * RANK) {
        float h = 0.0f;
        #pragma unroll
        for (int ww = 0; ww < NWARP; ww++) h += red[ww][tid];
        hs[tid] = h;                       // sA and 2/pi already folded into Aft
    }
    __syncthreads();

    // hoist h into registers
    float hreg[ROWS][RANK];
    #pragma unroll
    for (int rr = 0; rr < ROWS; rr++) {
        #pragma unroll
        for (int r = 0; r < RANK; r += 4) {
            const float4 hv = *(const float4*)(hs + rr * RANK + r);
            hreg[rr][r]     = hv.x;
            hreg[rr][r + 1] = hv.y;
            hreg[rr][r + 2] = hv.z;
            hreg[rr][r + 3] = hv.w;
        }
    }

    // ---- phase 2: y = x + 2*sin( sum_r hreg[row][r] * Bf[r][c] ) ----
    #pragma unroll
    for (int i = 0; i < 4; i++) {
        const int c0 = w * 512 + i * 128 + lane * 4;

        float acc2[ROWS][4];
        #pragma unroll
        for (int rr = 0; rr < ROWS; rr++)
            #pragma unroll
            for (int j = 0; j < 4; j++)
                acc2[rr][j] = 0.0f;

        #pragma unroll
        for (int r = 0; r < RANK; r++) {
            const float4 bv = *(const float4*)(g_Bf + (size_t)r * HIDDEN + c0);
            const float b[4] = {bv.x, bv.y, bv.z, bv.w};
            #pragma unroll
            for (int rr = 0; rr < ROWS; rr++) {
                const float hr = hreg[rr][r];
                #pragma unroll
                for (int j = 0; j < 4; j++)
                    acc2[rr][j] = fmaf(hr, b[j], acc2[rr][j]);
            }
        }

        #pragma unroll
        for (int rr = 0; rr < ROWS; rr++) {
            const float4 xv = *(const float4*)(xs + rr * HIDDEN + c0);
            float4 ov;
            ov.x = fmaf(2.0f, fast_sin(acc2[rr][0]), xv.x);
            ov.y = fmaf(2.0f, fast_sin(acc2[rr][1]), xv.y);
            ov.z = fmaf(2.0f, fast_sin(acc2[rr][2]), xv.z);
            ov.w = fmaf(2.0f, fast_sin(acc2[rr][3]), xv.w);
            *(float4*)(y + (rowbase + rr) * HIDDEN + c0) = ov;
        }
    }
}

extern "C" void kernel_launch(void* const* d_in, const int* in_sizes, int n_in,
                              void* d_out, int out_size)
{
    // Rank-order binding by size (robust; validated since R4)
    int idx[16];
    const int m = (n_in < 16) ? n_in : 16;
    for (int i = 0; i < m; i++) idx[i] = i;
    for (int i = 0; i < m; i++) {
        int best = i;
        for (int j = i + 1; j < m; j++)
            if (in_sizes[idx[j]] < in_sizes[idx[best]]) best = j;
        if (best != i) {
            int t = idx[best];
            for (int j = best; j > i; j--) idx[j] = idx[j - 1];
            idx[i] = t;
        }
    }
    const float* sA = (const float*)d_in[idx[0]];
    const float* sB = (const float*)d_in[idx[1]];
    const void*  A  = d_in[idx[2]];
    const void*  B  = d_in[idx[3]];
    const float* x  = (const float*)d_in[idx[m - 1]];
    float* y = (float*)d_out;

    prep_kernel<<<(HIDDEN * RANK) / 256, 256>>>(A, B, sA, sB);

    const size_t smem = (size_t)ROWS * HIDDEN * sizeof(float);   // 64 KB
    cudaFuncSetAttribute(pilora_kernel,
                         cudaFuncAttributeMaxDynamicSharedMemorySize, (int)smem);
    pilora_kernel<<<TOTAL_ROWS / ROWS, THREADS, smem>>>(x, y);
}